// round 5
// baseline (speedup 1.0000x reference)
#include <cuda_runtime.h>
#include <cuda_bf16.h>
#include <cstdint>

// ===========================================================================
// CR8_reg_cond_mul_5 — mma.sync (bf16 split precision) implementation.
// compute_100-portable: no tcgen05 (ptxas target is sm_100, not sm_100a).
//
//  class path:  x --W1--> h --cl2--> x2 --cl3--> logits[129]   (3-pass split)
//  reg path:    x --Wr--> r                                    (hi-only)
//  argmax in registers; ambiguous (gap<1e-3) recomputed in fp32.
//  tail: gathered [r;h] @ w2[super] (256x32) GEMV, bf16 inputs fp32 accum.
// ===========================================================================

#define NPOS  (16 * 8192)
#define RS    136          // bf16 plane row stride in elements
#define RSB   272          // bytes

// ---------------- device-global prepped data -------------------------------
__device__ float g_W1[128 * 128];              // BN-folded fp32 W1 (fallback)
__device__ float g_b1[128];
__device__ float g_br[128];
// bf16 hi/lo weight images, row-major [o][k], stride 128.
// layer offsets (elements): L0=0, L1=16384, L2=32768, L3=49152 (136 rows)
__device__ __nv_bfloat16 g_whi[66560];
__device__ __nv_bfloat16 g_wlo[66560];

__device__ __forceinline__ float lrelu(float v) { return v >= 0.0f ? v : 0.01f * v; }

__device__ __forceinline__ uint32_t pack2(float a, float b) {
    __nv_bfloat162 t(__float2bfloat16(a), __float2bfloat16(b));
    return *reinterpret_cast<uint32_t*>(&t);
}
__device__ __forceinline__ uint32_t pack2_res(float a, float b, float* ra, float* rb) {
    __nv_bfloat16 ha = __float2bfloat16(a), hb = __float2bfloat16(b);
    *ra = a - __bfloat162float(ha);
    *rb = b - __bfloat162float(hb);
    __nv_bfloat162 t(ha, hb);
    return *reinterpret_cast<uint32_t*>(&t);
}
__device__ __forceinline__ void unpack2(uint32_t u, float* a, float* b) {
    __nv_bfloat162 t = *reinterpret_cast<__nv_bfloat162*>(&u);
    *a = __bfloat162float(t.x);
    *b = __bfloat162float(t.y);
}

__device__ __forceinline__ void mma16816(float* d,
    uint32_t a0, uint32_t a1, uint32_t a2, uint32_t a3,
    uint32_t b0, uint32_t b1)
{
    asm volatile(
        "mma.sync.aligned.m16n8k16.row.col.f32.bf16.bf16.f32 "
        "{%0,%1,%2,%3}, {%4,%5,%6,%7}, {%8,%9}, {%0,%1,%2,%3};"
        : "+f"(d[0]), "+f"(d[1]), "+f"(d[2]), "+f"(d[3])
        : "r"(a0), "r"(a1), "r"(a2), "r"(a3), "r"(b0), "r"(b1));
}

// ---------------- smem layout (byte offsets) -------------------------------
#define OFF_XHI    0
#define OFF_XLO    34816
#define OFF_HHI    69632
#define OFF_HLO    104448
#define OFF_RHI    139264
#define OFF_WBUF   174080          // 136*RSB = 36992
#define OFF_B1     211072
#define OFF_BR     211584
#define OFF_BC2    212096
#define OFF_BC3    212608          // 136 floats
#define OFF_MASK   213184
#define OFF_INDS   213696
#define OFF_PERM   214208
#define OFF_CNT    214720
#define OFF_NFLAG  214784
#define OFF_FLAGW  214800
#define OFF_XCOL   215312
#define OFF_HCOL   215824
#define OFF_X2COL  216336
#define OFF_LGCOL  216848
#define SMEM_REQ   217600

// ---------------------------------------------------------------------------
// prep kernel: BN fold + bf16 hi/lo split (row-major images)
// ---------------------------------------------------------------------------
__global__ void prep_kernel(
    const float* __restrict__ cl1_w, const float* __restrict__ cl1_b,
    const float* __restrict__ g1, const float* __restrict__ bt1,
    const float* __restrict__ m1, const float* __restrict__ v1,
    const float* __restrict__ cl2_w,
    const float* __restrict__ cl3_w,
    const float* __restrict__ reg_w, const float* __restrict__ reg_b,
    const float* __restrict__ gr, const float* __restrict__ btr,
    const float* __restrict__ mr, const float* __restrict__ vr)
{
    int idx = blockIdx.x * blockDim.x + threadIdx.x;
    if (idx < 128) {
        float s1 = g1[idx] * rsqrtf(v1[idx] + 1e-5f);
        float sr = gr[idx] * rsqrtf(vr[idx] + 1e-5f);
        g_b1[idx] = (cl1_b[idx] - m1[idx]) * s1 + bt1[idx];
        g_br[idx] = (reg_b[idx] - mr[idx]) * sr + btr[idx];
    }
    if (idx >= 4 * 136 * 128) return;
    int L = idx / (136 * 128);
    int rem = idx % (136 * 128);
    int row = rem / 128, k = rem % 128;
    if (L != 3 && row >= 128) return;

    float v;
    if (L == 0) {
        float s = g1[row] * rsqrtf(v1[row] + 1e-5f);
        v = cl1_w[row * 128 + k] * s;
        g_W1[row * 128 + k] = v;
    } else if (L == 1) {
        float s = gr[row] * rsqrtf(vr[row] + 1e-5f);
        v = reg_w[row * 128 + k] * s;
    } else if (L == 2) {
        v = cl2_w[row * 128 + k];
    } else {
        v = (row < 129) ? cl3_w[row * 128 + k] : 0.0f;
    }
    __nv_bfloat16 hi = __float2bfloat16(v);
    __nv_bfloat16 lo = __float2bfloat16(v - __bfloat162float(hi));
    static const int loff[4] = {0, 16384, 32768, 49152};
    int dst = loff[L] + row * 128 + k;
    g_whi[dst] = hi;
    g_wlo[dst] = lo;
}

// ---------------------------------------------------------------------------
// main kernel helpers
// ---------------------------------------------------------------------------
__device__ __forceinline__ void copyW(const __nv_bfloat16* __restrict__ src,
                                      char* dst, int rows, int tid) {
    int total = rows * 16;                       // 16B chunks per 256B row
    const char* s = (const char*)src;
    for (int i = tid; i < total; i += 256) {
        int row = i >> 4, part = i & 15;
        *(uint4*)(dst + row * RSB + part * 16) =
            *(const uint4*)(s + row * 256 + part * 16);
    }
}

// One layer: acc[NT][4] += up to 3 passes of W x X (m16n8k16 tiling).
// Pass order: (Whi,Xhi), (Whi,Xlo), (Wlo,Xhi).
template <int NT>
__device__ __forceinline__ void run_layer(
    float (&acc)[NT][4],
    const char* xhi, const char* xlo,
    const __nv_bfloat16* gwhi, const __nv_bfloat16* gwlo,
    char* wbuf, int wrows, int npasses, int tid, int wp)
{
#pragma unroll
    for (int nt = 0; nt < NT; ++nt)
#pragma unroll
        for (int j = 0; j < 4; ++j) acc[nt][j] = 0.0f;

    const int lane = tid & 31;
    const int r = lane >> 2;                 // quad row 0..7
    const int cb = (lane & 3) * 2;           // col-pair base 0,2,4,6

    for (int pass = 0; pass < npasses; ++pass) {
        if (pass == 0) {
            __syncthreads();                 // prior readers of wbuf done
            copyW(gwhi, wbuf, wrows, tid);
            __syncthreads();
        } else if (pass == 2) {
            __syncthreads();
            copyW(gwlo, wbuf, wrows, tid);
            __syncthreads();
        }
        const char* X = (pass == 1) ? xlo : xhi;
        const char* arow = X + ((wp * 16 + r) * RS + cb) * 2;
#pragma unroll
        for (int kc = 0; kc < 8; ++kc) {
            const char* ab = arow + kc * 32;
            uint32_t a0 = *(const uint32_t*)(ab);
            uint32_t a1 = *(const uint32_t*)(ab + 8 * RSB);
            uint32_t a2 = *(const uint32_t*)(ab + 16);
            uint32_t a3 = *(const uint32_t*)(ab + 8 * RSB + 16);
            const char* bb0 = wbuf + (r * RS + kc * 16 + cb) * 2;
#pragma unroll
            for (int nt = 0; nt < NT; ++nt) {
                const char* bb = bb0 + nt * 8 * RSB;
                uint32_t b0 = *(const uint32_t*)(bb);
                uint32_t b1 = *(const uint32_t*)(bb + 16);
                mma16816(acc[nt], a0, a1, a2, a3, b0, b1);
            }
        }
    }
}

// epilogue: bias + lrelu, store bf16 hi (and optional lo residual) planes
__device__ __forceinline__ void epi_store(
    float (&acc)[16][4], const float* bias,
    char* dsthi, char* dstlo, int tid, int wp)
{
    const int lane = tid & 31;
    const int r = lane >> 2, cb = (lane & 3) * 2;
    const int p1 = wp * 16 + r, p2 = p1 + 8;
#pragma unroll
    for (int nt = 0; nt < 16; ++nt) {
        int o = nt * 8 + cb;
        float b0 = bias[o], b1 = bias[o + 1];
        float v0 = lrelu(acc[nt][0] + b0), v1 = lrelu(acc[nt][1] + b1);
        float v2 = lrelu(acc[nt][2] + b0), v3 = lrelu(acc[nt][3] + b1);
        if (dstlo) {
            float r0, r1, r2, r3;
            *(uint32_t*)(dsthi + p1 * RSB + o * 2) = pack2_res(v0, v1, &r0, &r1);
            *(uint32_t*)(dsthi + p2 * RSB + o * 2) = pack2_res(v2, v3, &r2, &r3);
            *(uint32_t*)(dstlo + p1 * RSB + o * 2) = pack2(r0, r1);
            *(uint32_t*)(dstlo + p2 * RSB + o * 2) = pack2(r2, r3);
        } else {
            *(uint32_t*)(dsthi + p1 * RSB + o * 2) = pack2(v0, v1);
            *(uint32_t*)(dsthi + p2 * RSB + o * 2) = pack2(v2, v3);
        }
    }
}

// ---------------------------------------------------------------------------
__global__ void __launch_bounds__(256, 1)
main_kernel(const float* __restrict__ x_in,
            const float* __restrict__ cl2_w, const float* __restrict__ cl2_b,
            const float* __restrict__ cl3_w, const float* __restrict__ cl3_b,
            const float* __restrict__ w2,    const float* __restrict__ b2,
            const float* __restrict__ w3,    const float* __restrict__ b3,
            float* __restrict__ out)
{
    extern __shared__ char sm[];
    char* Xhi = sm + OFF_XHI;
    char* Xlo = sm + OFF_XLO;
    char* Hhi = sm + OFF_HHI;
    char* Hlo = sm + OFF_HLO;
    char* Rhi = sm + OFF_RHI;
    char* Wbuf = sm + OFF_WBUF;
    float* b1s   = (float*)(sm + OFF_B1);
    float* brs   = (float*)(sm + OFF_BR);
    float* bc2   = (float*)(sm + OFF_BC2);
    float* bc3   = (float*)(sm + OFF_BC3);
    float* maskv = (float*)(sm + OFF_MASK);
    int*   inds  = (int*)(sm + OFF_INDS);
    int*   perm  = (int*)(sm + OFF_PERM);
    int*   cnt   = (int*)(sm + OFF_CNT);
    int*   nflag = (int*)(sm + OFF_NFLAG);
    int*   flagw = (int*)(sm + OFF_FLAGW);
    float* xcol  = (float*)(sm + OFF_XCOL);
    float* hcol  = (float*)(sm + OFF_HCOL);
    float* x2col = (float*)(sm + OFF_X2COL);
    float* lgcol = (float*)(sm + OFF_LGCOL);

    const int tid = threadIdx.x;
    const int wp  = tid >> 5;
    const int tile = blockIdx.x;
    const int b    = tile >> 6;
    const int w0   = (tile & 63) * 128;
    const float* xb = x_in + (size_t)b * 128 * 8192 + w0;

    // ---- stage X transposed (Xt[p][k]) as bf16 hi/lo; stage biases -------
    {
        int w = tid & 127;
        int cbase = tid >> 7;
        for (int c = cbase; c < 128; c += 2) {
            float v = xb[c * 8192 + w];
            __nv_bfloat16 hi = __float2bfloat16(v);
            float res = v - __bfloat162float(hi);
            *(__nv_bfloat16*)(Xhi + w * RSB + c * 2) = hi;
            *(__nv_bfloat16*)(Xlo + w * RSB + c * 2) = __float2bfloat16(res);
        }
    }
    if (tid < 128) {
        b1s[tid] = g_b1[tid];
        brs[tid] = g_br[tid];
        bc2[tid] = cl2_b[tid];
        bc3[tid] = cl3_b[tid];
    } else if (tid < 136) {
        bc3[tid] = (tid == 128) ? cl3_b[128] : 0.0f;
    }
    if (tid == 0) *nflag = 0;
    if (tid < 16) cnt[tid] = 0;
    // run_layer's leading __syncthreads() orders the staging.

    const __nv_bfloat16* W0h = g_whi;            const __nv_bfloat16* W0l = g_wlo;
    const __nv_bfloat16* W1h = g_whi + 16384;
    const __nv_bfloat16* W2h = g_whi + 32768;    const __nv_bfloat16* W2l = g_wlo + 32768;
    const __nv_bfloat16* W3h = g_whi + 49152;    const __nv_bfloat16* W3l = g_wlo + 49152;

    {   // L0: h = lrelu(W1 x)   [3-pass]
        float acc[16][4];
        run_layer<16>(acc, Xhi, Xlo, W0h, W0l, Wbuf, 128, 3, tid, wp);
        epi_store(acc, b1s, Hhi, Hlo, tid, wp);
    }
    {   // L1: r = lrelu(Wr x)   [hi-only]
        float acc[16][4];
        run_layer<16>(acc, Xhi, Xlo, W1h, W1h, Wbuf, 128, 1, tid, wp);
        epi_store(acc, brs, Rhi, nullptr, tid, wp);
    }
    {   // L2: x2 = lrelu(cl2 h) [3-pass] -> overwrites X planes
        float acc[16][4];
        run_layer<16>(acc, Hhi, Hlo, W2h, W2l, Wbuf, 128, 3, tid, wp);
        epi_store(acc, bc2, Xhi, Xlo, tid, wp);
    }
    {   // L3: logits = cl3 x2   [3-pass, 136 padded outputs] + argmax epi
        float acc[17][4];
        run_layer<17>(acc, Xhi, Xlo, W3h, W3l, Wbuf, 136, 3, tid, wp);

        const int lane = tid & 31;
        const int r = lane >> 2, cb = (lane & 3) * 2;
        const int p1 = wp * 16 + r, p2 = p1 + 8;
        float bst1 = -3.4e38f, sec1 = -3.4e38f, bst2 = -3.4e38f, sec2 = -3.4e38f;
        int i1 = 0, i2 = 0;
        float m1v = 0.0f, m2v = 0.0f;
#pragma unroll
        for (int nt = 0; nt < 17; ++nt) {
            int o0 = nt * 8 + cb, o1 = o0 + 1;
            float v0 = acc[nt][0] + bc3[o0], v1 = acc[nt][1] + bc3[o1];
            float v2 = acc[nt][2] + bc3[o0], v3 = acc[nt][3] + bc3[o1];
            if (o0 < 128) {
                if (v0 > bst1) { sec1 = bst1; bst1 = v0; i1 = o0; } else if (v0 > sec1) sec1 = v0;
                if (v2 > bst2) { sec2 = bst2; bst2 = v2; i2 = o0; } else if (v2 > sec2) sec2 = v2;
            } else if (o0 == 128) { m1v = v0; m2v = v2; }
            if (o1 < 128) {
                if (v1 > bst1) { sec1 = bst1; bst1 = v1; i1 = o1; } else if (v1 > sec1) sec1 = v1;
                if (v3 > bst2) { sec2 = bst2; bst2 = v3; i2 = o1; } else if (v3 > sec2) sec2 = v3;
            }
        }
#pragma unroll
        for (int off = 1; off < 4; off <<= 1) {
            float ob = __shfl_xor_sync(0xFFFFFFFFu, bst1, off);
            float os = __shfl_xor_sync(0xFFFFFFFFu, sec1, off);
            int   oi = __shfl_xor_sync(0xFFFFFFFFu, i1,  off);
            if (ob > bst1 || (ob == bst1 && oi < i1)) { sec1 = fmaxf(bst1, os); bst1 = ob; i1 = oi; }
            else sec1 = fmaxf(sec1, ob);
            ob = __shfl_xor_sync(0xFFFFFFFFu, bst2, off);
            os = __shfl_xor_sync(0xFFFFFFFFu, sec2, off);
            oi = __shfl_xor_sync(0xFFFFFFFFu, i2,  off);
            if (ob > bst2 || (ob == bst2 && oi < i2)) { sec2 = fmaxf(bst2, os); bst2 = ob; i2 = oi; }
            else sec2 = fmaxf(sec2, ob);
        }
        if ((lane & 3) == 0) {
            inds[p1] = i1; inds[p2] = i2;
            maskv[p1] = lrelu(m1v); maskv[p2] = lrelu(m2v);
            if (bst1 - sec1 < 1e-3f) { int p = atomicAdd(nflag, 1); if (p < 128) flagw[p] = p1; }
            if (bst2 - sec2 < 1e-3f) { int p = atomicAdd(nflag, 1); if (p < 128) flagw[p] = p2; }
        }
    }
    __syncthreads();

    // ---- fp32 fallback for ambiguous argmax (rare) -----------------------
    int nf = *nflag; if (nf > 128) nf = 128;
    for (int i = 0; i < nf; ++i) {
        int w = flagw[i];
        if (tid < 128) xcol[tid] = xb[tid * 8192 + w];
        __syncthreads();
        {
            int o = tid >> 1, hh = tid & 1;
            const float* Wp = g_W1 + o * 128 + hh * 64;
            const float* xc = xcol + hh * 64;
            float s = 0.0f;
#pragma unroll 8
            for (int c = 0; c < 64; ++c) s = fmaf(Wp[c], xc[c], s);
            s += __shfl_xor_sync(0xFFFFFFFFu, s, 1);
            if (hh == 0) hcol[o] = lrelu(s + b1s[o]);
        }
        __syncthreads();
        {
            int o = tid >> 1, hh = tid & 1;
            const float* Wp = cl2_w + o * 128 + hh * 64;
            const float* xc = hcol + hh * 64;
            float s = 0.0f;
#pragma unroll 8
            for (int c = 0; c < 64; ++c) s = fmaf(Wp[c], xc[c], s);
            s += __shfl_xor_sync(0xFFFFFFFFu, s, 1);
            if (hh == 0) x2col[o] = lrelu(s + bc2[o]);
        }
        __syncthreads();
        {
            int o = tid >> 1, hh = tid & 1;
            const float* Wp = cl3_w + o * 128 + hh * 64;
            const float* xc = x2col + hh * 64;
            float s = 0.0f;
#pragma unroll 8
            for (int c = 0; c < 64; ++c) s = fmaf(Wp[c], xc[c], s);
            s += __shfl_xor_sync(0xFFFFFFFFu, s, 1);
            if (hh == 0) lgcol[o] = s + bc3[o];
        }
        __syncthreads();
        if (tid == 0) {
            float bv = lgcol[0]; int bi = 0;
            for (int o = 1; o < 128; ++o)
                if (lgcol[o] > bv) { bv = lgcol[o]; bi = o; }
            inds[w] = bi;
        }
        __syncthreads();
    }

    // ---- counting sort by super ------------------------------------------
    if (tid < 128) atomicAdd(&cnt[inds[tid] >> 4], 1);
    __syncthreads();
    if (tid == 0) {
        int run = 0;
#pragma unroll
        for (int s = 0; s < 8; ++s) { cnt[8 + s] = run; run += cnt[s]; }
    }
    __syncthreads();
    if (tid < 128) {
        int s = inds[tid] >> 4;
        int p = atomicAdd(&cnt[8 + s], 1);
        perm[p] = tid;
    }
    __syncthreads();

    // ---- gathered 256x32 GEMV + regression (bf16 h/r, fp32 accum) --------
    {
        const int pr = tid >> 1, t2 = tid & 1;
        const int w = perm[pr];
        const int ind = inds[w];
        const int s = ind >> 4;
        const char* plane = t2 ? Hhi : Rhi;
        const char* prow = plane + w * RSB;
        const float* w2p = w2 + ((size_t)s * 256 + (size_t)t2 * 128) * 32;

        float acc[32];
#pragma unroll
        for (int o = 0; o < 32; ++o) acc[o] = 0.0f;

        for (int f2 = 0; f2 < 64; ++f2) {
            float v0, v1;
            unpack2(*(const uint32_t*)(prow + f2 * 4), &v0, &v1);
            const float4* wr0 = (const float4*)(w2p + (2 * f2) * 32);
            const float4* wr1 = (const float4*)(w2p + (2 * f2 + 1) * 32);
#pragma unroll
            for (int q = 0; q < 8; ++q) {
                float4 t0 = wr0[q];
                acc[q * 4 + 0] = fmaf(v0, t0.x, acc[q * 4 + 0]);
                acc[q * 4 + 1] = fmaf(v0, t0.y, acc[q * 4 + 1]);
                acc[q * 4 + 2] = fmaf(v0, t0.z, acc[q * 4 + 2]);
                acc[q * 4 + 3] = fmaf(v0, t0.w, acc[q * 4 + 3]);
            }
#pragma unroll
            for (int q = 0; q < 8; ++q) {
                float4 t1 = wr1[q];
                acc[q * 4 + 0] = fmaf(v1, t1.x, acc[q * 4 + 0]);
                acc[q * 4 + 1] = fmaf(v1, t1.y, acc[q * 4 + 1]);
                acc[q * 4 + 2] = fmaf(v1, t1.z, acc[q * 4 + 2]);
                acc[q * 4 + 3] = fmaf(v1, t1.w, acc[q * 4 + 3]);
            }
        }
#pragma unroll
        for (int o = 0; o < 32; ++o)
            acc[o] += __shfl_xor_sync(0xFFFFFFFFu, acc[o], 1);

        float reg = b3[ind];
        const float* b2p = b2 + s * 32;
        const float* w3p = w3 + ind * 32;
#pragma unroll
        for (int o = 0; o < 32; ++o) {
            float y = lrelu(acc[o] + b2p[o]);
            reg = fmaf(y, w3p[o], reg);
        }
        if (t2 == 0) {
            int n = b * 8192 + w0 + w;
            out[n] = ((float)ind + reg) * (1.0f / 128.0f);
            out[NPOS + n] = maskv[w];
        }
    }
}

// ---------------------------------------------------------------------------
extern "C" void kernel_launch(void* const* d_in, const int* in_sizes, int n_in,
                              void* d_out, int out_size)
{
    (void)in_sizes; (void)n_in; (void)out_size;
    const float* x_in   = (const float*)d_in[0];
    const float* cl1_w  = (const float*)d_in[1];
    const float* cl1_b  = (const float*)d_in[2];
    const float* cl1_g  = (const float*)d_in[3];
    const float* cl1_bt = (const float*)d_in[4];
    const float* cl1_m  = (const float*)d_in[5];
    const float* cl1_v  = (const float*)d_in[6];
    const float* cl2_w  = (const float*)d_in[7];
    const float* cl2_b  = (const float*)d_in[8];
    const float* cl3_w  = (const float*)d_in[9];
    const float* cl3_b  = (const float*)d_in[10];
    const float* reg1_w = (const float*)d_in[11];
    const float* reg1_b = (const float*)d_in[12];
    const float* reg1_g = (const float*)d_in[13];
    const float* reg1_bt= (const float*)d_in[14];
    const float* reg1_m = (const float*)d_in[15];
    const float* reg1_v = (const float*)d_in[16];
    const float* w2     = (const float*)d_in[17];
    const float* b2     = (const float*)d_in[18];
    const float* w3     = (const float*)d_in[19];
    const float* b3     = (const float*)d_in[20];
    float* out = (float*)d_out;

    cudaFuncSetAttribute(main_kernel,
                         cudaFuncAttributeMaxDynamicSharedMemorySize, SMEM_REQ);

    prep_kernel<<<(4 * 136 * 128 + 255) / 256, 256>>>(
        cl1_w, cl1_b, cl1_g, cl1_bt, cl1_m, cl1_v,
        cl2_w, cl3_w,
        reg1_w, reg1_b, reg1_g, reg1_bt, reg1_m, reg1_v);

    main_kernel<<<1024, 256, SMEM_REQ>>>(x_in, cl2_w, cl2_b, cl3_w, cl3_b,
                                         w2, b2, w3, b3, out);
}